// round 12
// baseline (speedup 1.0000x reference)
#include <cuda_runtime.h>

typedef unsigned long long ull;

__device__ __forceinline__ ull pack2(float lo, float hi) {
    ull r; asm("mov.b64 %0, {%1, %2};" : "=l"(r) : "f"(lo), "f"(hi)); return r;
}
__device__ __forceinline__ void unpack2(ull v, float& lo, float& hi) {
    asm("mov.b64 {%0, %1}, %2;" : "=f"(lo), "=f"(hi) : "l"(v));
}
__device__ __forceinline__ void fma2(ull& d, ull a, ull b) {
    asm("fma.rn.f32x2 %0, %1, %2, %0;" : "+l"(d) : "l"(a), "l"(b));
}
__device__ __forceinline__ float ex2f(float x) {
    float y; asm("ex2.approx.f32 %0, %1;" : "=f"(y) : "f"(x)); return y;
}

// ---------------- scratch (no allocations allowed) ----------------
#define NTOK (2*4096)              // 8192 tokens
#define PBUF (NTOK*64)             // 524288 floats per partial buffer
__device__ float  g_p[4*PBUF];     // conv1 partials (per ci-quarter)
__device__ float  g_q[4*PBUF];     // conv2 partials (per ci-quarter)
__device__ float  g_wt1[64*9*64];  // [ci][k][(co2,s)]: pair = (co2, co2+32)
__device__ float  g_wt2[64*9*64];
__device__ float  g_tt[NTOK*64];   // t (conv2 out, NHWC)
__device__ float  g_qh[NTOK*64];   // normalized q (LOG2E folded)
__device__ float2 g_kv[NTOK*64];   // interleaved {k_hat, v}

// ---- prep: [co][ci][3][3] -> [ci][k][(co2,s)] where pair = (co2, co2+32) ----
__global__ void k_transpose_w(const float* __restrict__ w1, const float* __restrict__ w2) {
    int i = blockIdx.x * blockDim.x + threadIdx.x;
    if (i >= 2 * 36864) return;
    const float* w = (i < 36864) ? w1 : w2;
    float* dst     = (i < 36864) ? g_wt1 : g_wt2;
    int o   = (i < 36864) ? i : (i - 36864);
    int ci  = o / 576;
    int rem = o - ci * 576;
    int kk  = rem >> 6;
    int qq  = rem & 63;
    int co2 = qq >> 1;
    int s   = qq & 1;
    dst[o] = w[(s * 32 + co2) * 576 + ci * 9 + kk];
}

// ---------------- partial conv3x3: 16 ci x 64 co per block (R11, unchanged) ------
#define IN_CI_STRIDE 148
template<int SRC>
__global__ void __launch_bounds__(256, 3) k_conv(const float* __restrict__ in_x,
                                                 const float* __restrict__ in_bias) {
    const float* __restrict__ wt = (SRC == 0) ? g_wt1 : g_wt2;

    __shared__ float w_s[16 * 576];
    __shared__ float in_s[16 * IN_CI_STRIDE];

    const int tid = threadIdx.x;
    const int co2 = tid & 31;
    const int h   = tid >> 5;
    const int x0 = blockIdx.x * 32, y0 = blockIdx.y * 2;
    const int b       = blockIdx.z >> 2;
    const int quarter = blockIdx.z & 3;

    {
        const float4* wsrc = (const float4*)(wt + quarter * 16 * 576);
        float4* wdst = (float4*)w_s;
#pragma unroll
        for (int i = 0; i < 9; i++)
            wdst[tid + i * 256] = wsrc[tid + i * 256];
    }
    if (SRC == 0) {
#pragma unroll
        for (int i = 0; i < 9; i++) {
            int e = i * 256 + tid;
            if (e < 2176) {
                int xx = e % 34;
                int t  = e / 34;
                int r  = t & 3;
                int ci = t >> 2;
                int y  = y0 - 1 + r;
                int xg = x0 - 1 + xx;
                float v = 0.f;
                if ((unsigned)y < 64u && (unsigned)xg < 64u)
                    v = in_x[((b * 64 + quarter * 16 + ci) * 64 + y) * 64 + xg];
                in_s[ci * IN_CI_STRIDE + r * 36 + xx] = v;
            }
        }
    } else {
        const int ci = tid & 15;
        const float bvin = in_bias[quarter * 16 + ci];
#pragma unroll
        for (int i = 0; i < 9; i++) {
            int e = i * 256 + tid;
            if (e < 2176) {
                int t  = e >> 4;
                int r  = t / 34;
                int xx = t - r * 34;
                int y  = y0 - 1 + r;
                int xg = x0 - 1 + xx;
                float v = 0.f;
                if ((unsigned)y < 64u && (unsigned)xg < 64u) {
                    int idx = ((b * 64 + y) * 64 + xg) * 64 + quarter * 16 + ci;
                    float s0 = g_p[idx]          + g_p[idx + PBUF];
                    float s1 = g_p[idx + 2*PBUF] + g_p[idx + 3*PBUF];
                    v = fmaxf(s0 + s1 + bvin, 0.f);
                }
                in_s[ci * IN_CI_STRIDE + r * 36 + xx] = v;
            }
        }
    }
    __syncthreads();

    ull accA[4] = {0,0,0,0};
    ull accB[4] = {0,0,0,0};

#pragma unroll 4
    for (int ci = 0; ci < 16; ci++) {
        const ull* wp = (const ull*)(w_s + ci * 576) + co2;
        ull w2[9];
#pragma unroll
        for (int k = 0; k < 9; k++) w2[k] = wp[k * 32];

        const float* ibase = in_s + ci * IN_CI_STRIDE + h * 4;
#pragma unroll
        for (int irow = 0; irow < 4; irow++) {
            float4 v0 = *(const float4*)(ibase + irow * 36);
            float2 v1 = *(const float2*)(ibase + irow * 36 + 4);
            ull d[6];
            d[0] = pack2(v0.x, v0.x); d[1] = pack2(v0.y, v0.y);
            d[2] = pack2(v0.z, v0.z); d[3] = pack2(v0.w, v0.w);
            d[4] = pack2(v1.x, v1.x); d[5] = pack2(v1.y, v1.y);
            if (irow < 3) {
#pragma unroll
                for (int p = 0; p < 4; p++) {
                    fma2(accA[p], w2[irow*3+0], d[p]);
                    fma2(accA[p], w2[irow*3+1], d[p+1]);
                    fma2(accA[p], w2[irow*3+2], d[p+2]);
                }
            }
            if (irow >= 1) {
#pragma unroll
                for (int p = 0; p < 4; p++) {
                    fma2(accB[p], w2[(irow-1)*3+0], d[p]);
                    fma2(accB[p], w2[(irow-1)*3+1], d[p+1]);
                    fma2(accB[p], w2[(irow-1)*3+2], d[p+2]);
                }
            }
        }
    }

    float* __restrict__ out = ((SRC == 0) ? g_p : g_q) + quarter * PBUF;
    int base = ((b * 64 + y0) * 64 + x0 + h * 4) * 64;
#pragma unroll
    for (int p = 0; p < 4; p++) {
        float a0, a1, b0v, b1v;
        unpack2(accA[p], a0, a1);
        unpack2(accB[p], b0v, b1v);
        out[base + p * 64 + co2]             = a0;
        out[base + p * 64 + co2 + 32]        = a1;
        out[base + 4096 + p * 64 + co2]      = b0v;
        out[base + 4096 + p * 64 + co2 + 32] = b1v;
    }
}

// ---------------- k_proj: t + q/k/v projections + norms -> global ----------------
// 32 tokens/block, 256 threads (tt = tid&31, cg = tid>>5, 8 ch each)
#define A_WQ 0
#define A_WK 4224
#define A_WV 8448
#define A_T  12672
#define A_Q  14752
#define A_KV 16832                 // float2 region, [32][65]
#define A_SQ 20992
#define A_SK 21256
#define A_FLOATS 21520             // 84.1 KB

__global__ void __launch_bounds__(256) k_proj(
    const float* __restrict__ wq, const float* __restrict__ wk,
    const float* __restrict__ wv, const float* __restrict__ b2)
{
    extern __shared__ float sm[];
    float*  wq_s = sm + A_WQ;      // [l][c], stride 66
    float*  wk_s = sm + A_WK;
    float*  wv_s = sm + A_WV;
    float*  t_s  = sm + A_T;       // [32][65]
    float*  q_s  = sm + A_Q;
    float2* kv_s = (float2*)(sm + A_KV);   // [32][65]
    float*  sq_s = sm + A_SQ;
    float*  sk_s = sm + A_SK;

    int tid = threadIdx.x;
    int n0  = blockIdx.x * 32;

#pragma unroll 4
    for (int i = 0; i < 16; i++) {
        int gg = tid + i * 256;
        int c = gg >> 6, l = gg & 63;
        wq_s[l * 66 + c] = wq[gg];
        wk_s[l * 66 + c] = wk[gg];
        wv_s[l * 66 + c] = wv[gg];
    }
#pragma unroll
    for (int i = 0; i < 8; i++) {
        int gg = tid + i * 256;
        int idx = n0 * 64 + gg;
        float s0 = g_q[idx]          + g_q[idx + PBUF];
        float s1 = g_q[idx + 2*PBUF] + g_q[idx + 3*PBUF];
        t_s[(gg >> 6) * 65 + (gg & 63)] = s0 + s1 + b2[gg & 63];
    }
    __syncthreads();

    const int tt = tid & 31;
    const int cg = tid >> 5;
    const int c0 = cg * 8;

    ull q2[4], k2[4], v2[4];
#pragma unroll
    for (int j = 0; j < 4; j++) { q2[j] = 0ull; k2[j] = 0ull; v2[j] = 0ull; }
    const float* trow = t_s + tt * 65;
#pragma unroll 4
    for (int l = 0; l < 64; l++) {
        float tl = trow[l];
        ull tl2 = pack2(tl, tl);
        const ull* wql = (const ull*)(wq_s + l * 66 + c0);
        const ull* wkl = (const ull*)(wk_s + l * 66 + c0);
        const ull* wvl = (const ull*)(wv_s + l * 66 + c0);
#pragma unroll
        for (int j = 0; j < 4; j++) {
            fma2(q2[j], tl2, wql[j]);
            fma2(k2[j], tl2, wkl[j]);
            fma2(v2[j], tl2, wvl[j]);
        }
    }
    float q[8], kk[8], vv[8];
#pragma unroll
    for (int j = 0; j < 4; j++) {
        unpack2(q2[j], q[2*j], q[2*j+1]);
        unpack2(k2[j], kk[2*j], kk[2*j+1]);
        unpack2(v2[j], vv[2*j], vv[2*j+1]);
    }
    float sq = 0.f, sk = 0.f;
#pragma unroll
    for (int j = 0; j < 8; j++) { sq = fmaf(q[j], q[j], sq); sk = fmaf(kk[j], kk[j], sk); }
    sq_s[cg * 33 + tt] = sq;
    sk_s[cg * 33 + tt] = sk;
    __syncthreads();
    sq = 0.f; sk = 0.f;
#pragma unroll
    for (int m = 0; m < 8; m++) { sq += sq_s[m * 33 + tt]; sk += sk_s[m * 33 + tt]; }
    const float LOG2E = 1.4426950408889634f;
    float invq = LOG2E / fmaxf(sqrtf(sq), 1e-12f);
    float invk = 1.0f  / fmaxf(sqrtf(sk), 1e-12f);
#pragma unroll
    for (int j = 0; j < 8; j++) {
        q_s[tt * 65 + c0 + j]  = q[j] * invq;
        kv_s[tt * 65 + c0 + j] = make_float2(kk[j] * invk, vv[j]);
    }
    __syncthreads();

    // coalesced write-out
#pragma unroll
    for (int i = 0; i < 8; i++) {
        int gg = tid + i * 256;
        int row = gg >> 6, col = gg & 63;
        g_qh[n0 * 64 + gg] = q_s[row * 65 + col];
        g_tt[n0 * 64 + gg] = t_s[row * 65 + col];
        g_kv[n0 * 64 + gg] = kv_s[row * 65 + col];
    }
}

// ---------------- k_attn2: rank-1 softmax + Wo + residual ----------------
// 32 tokens/block, 512 threads (tt = tid&31, cg = tid>>5 in 0..15, 4 ch each)
#define B_WO 0
#define B_T  4224
#define B_Q  6304
#define B_O  8384
#define B_KV 10464                 // float2 region, [32][65]
#define B_FLOATS 14624             // 58.5 KB

__global__ void __launch_bounds__(512) k_attn2(
    const float* __restrict__ wo, const float* __restrict__ bo,
    float* __restrict__ out)
{
    extern __shared__ float sm[];
    float*  wo_s = sm + B_WO;      // [c][c'], stride 66
    float*  t_s  = sm + B_T;       // [32][65]
    float*  q_s  = sm + B_Q;
    float*  o_s  = sm + B_O;
    float2* kv_s = (float2*)(sm + B_KV);

    int tid = threadIdx.x;
    int n0  = blockIdx.x * 32;

#pragma unroll
    for (int i = 0; i < 8; i++) {
        int gg = tid + i * 512;
        wo_s[(gg & 63) * 66 + (gg >> 6)] = wo[gg];   // transposed: [l][c']
    }
#pragma unroll
    for (int i = 0; i < 4; i++) {
        int gg = tid + i * 512;
        int row = gg >> 6, col = gg & 63;
        t_s[row * 65 + col]  = g_tt[n0 * 64 + gg];
        q_s[row * 65 + col]  = g_qh[n0 * 64 + gg];
        kv_s[row * 65 + col] = g_kv[n0 * 64 + gg];
    }
    __syncthreads();

    const int tt = tid & 31;
    const int cg = tid >> 5;       // 0..15
    const int c0 = cg * 4;

    float q[4];
#pragma unroll
    for (int j = 0; j < 4; j++) q[j] = q_s[tt * 65 + c0 + j];

    // packed num/den: nd = {num, den}; fma2(nd, {e,e}, {vd, 1})
    ull nd[4] = {0ull, 0ull, 0ull, 0ull};
    const float2* kvrow = kv_s + tt * 65;
#pragma unroll 4
    for (int d = 0; d < 64; d++) {
        float2 kv = kvrow[d];
        ull vd2 = pack2(kv.y, 1.0f);
#pragma unroll
        for (int j = 0; j < 4; j++) {
            float e = ex2f(q[j] * kv.x);
            fma2(nd[j], pack2(e, e), vd2);
        }
    }
#pragma unroll
    for (int j = 0; j < 4; j++) {
        float num, den;
        unpack2(nd[j], num, den);
        o_s[tt * 65 + c0 + j] = __fdividef(num, den);
    }
    __syncthreads();

    ull fin2[2] = {0ull, 0ull};
    const float* orow = o_s + tt * 65;
#pragma unroll 4
    for (int c = 0; c < 64; c++) {
        float oc = orow[c];
        ull oc2 = pack2(oc, oc);
        const ull* wol = (const ull*)(wo_s + c * 66 + c0);
        fma2(fin2[0], oc2, wol[0]);
        fma2(fin2[1], oc2, wol[1]);
    }
    int b = n0 >> 12;
    int s = (n0 & 4095) + tt;
#pragma unroll
    for (int j = 0; j < 2; j++) {
        float f0, f1;
        unpack2(fin2[j], f0, f1);
        int ch = c0 + 2 * j;
        f0 += bo[ch]     + t_s[tt * 65 + ch];
        f1 += bo[ch + 1] + t_s[tt * 65 + ch + 1];
        out[(b * 64 + ch    ) * 4096 + s] = f0;
        out[(b * 64 + ch + 1) * 4096 + s] = f1;
    }
}

// ---------------- launch ----------------
extern "C" void kernel_launch(void* const* d_in, const int* in_sizes, int n_in,
                              void* d_out, int out_size) {
    const float* x  = (const float*)d_in[0];
    const float* w1 = (const float*)d_in[1];
    const float* b1 = (const float*)d_in[2];
    const float* w2 = (const float*)d_in[3];
    const float* b2 = (const float*)d_in[4];
    const float* wq = (const float*)d_in[5];
    const float* wk = (const float*)d_in[6];
    const float* wv = (const float*)d_in[7];
    const float* wo = (const float*)d_in[8];
    const float* bo = (const float*)d_in[9];
    float* out = (float*)d_out;

    cudaFuncSetAttribute(k_proj, cudaFuncAttributeMaxDynamicSharedMemorySize,
                         A_FLOATS * (int)sizeof(float));
    cudaFuncSetAttribute(k_attn2, cudaFuncAttributeMaxDynamicSharedMemorySize,
                         B_FLOATS * (int)sizeof(float));

    k_transpose_w<<<(2 * 36864 + 255) / 256, 256>>>(w1, w2);
    k_conv<0><<<dim3(2, 32, 8), dim3(256)>>>(x, b1);
    k_conv<1><<<dim3(2, 32, 8), dim3(256)>>>(x, b1);
    k_proj<<<256, 256, A_FLOATS * (int)sizeof(float)>>>(wq, wk, wv, b2);
    k_attn2<<<256, 512, B_FLOATS * (int)sizeof(float)>>>(wo, bo, out);
}

// round 13
// speedup vs baseline: 1.0482x; 1.0482x over previous
#include <cuda_runtime.h>

typedef unsigned long long ull;

__device__ __forceinline__ ull pack2(float lo, float hi) {
    ull r; asm("mov.b64 %0, {%1, %2};" : "=l"(r) : "f"(lo), "f"(hi)); return r;
}
__device__ __forceinline__ void unpack2(ull v, float& lo, float& hi) {
    asm("mov.b64 {%0, %1}, %2;" : "=f"(lo), "=f"(hi) : "l"(v));
}
__device__ __forceinline__ void fma2(ull& d, ull a, ull b) {
    asm("fma.rn.f32x2 %0, %1, %2, %0;" : "+l"(d) : "l"(a), "l"(b));
}
__device__ __forceinline__ float ex2f(float x) {
    float y; asm("ex2.approx.f32 %0, %1;" : "=f"(y) : "f"(x)); return y;
}

// ---------------- scratch (no allocations allowed) ----------------
#define NTOK (2*4096)              // 8192 tokens
#define PBUF (NTOK*64)             // 524288 floats per partial buffer
__device__ float g_p[4*PBUF];      // conv1 partials (per ci-quarter)
__device__ float g_q[4*PBUF];      // conv2 partials (per ci-quarter)
__device__ float g_wt1[64*9*64];   // [ci][k][(co2,s)]: pair = (co2, co2+32)
__device__ float g_wt2[64*9*64];

// ---- prep: [co][ci][3][3] -> [ci][k][(co2,s)] where pair = (co2, co2+32) ----
__global__ void k_transpose_w(const float* __restrict__ w1, const float* __restrict__ w2) {
    int i = blockIdx.x * blockDim.x + threadIdx.x;
    if (i >= 2 * 36864) return;
    const float* w = (i < 36864) ? w1 : w2;
    float* dst     = (i < 36864) ? g_wt1 : g_wt2;
    int o   = (i < 36864) ? i : (i - 36864);
    int ci  = o / 576;
    int rem = o - ci * 576;
    int kk  = rem >> 6;
    int qq  = rem & 63;
    int co2 = qq >> 1;
    int s   = qq & 1;
    dst[o] = w[(s * 32 + co2) * 576 + ci * 9 + kk];
}

// ---------------- partial conv3x3: 16 ci x 64 co per block (R11, unchanged) ------
#define IN_CI_STRIDE 148
template<int SRC>
__global__ void __launch_bounds__(256, 3) k_conv(const float* __restrict__ in_x,
                                                 const float* __restrict__ in_bias) {
    const float* __restrict__ wt = (SRC == 0) ? g_wt1 : g_wt2;

    __shared__ float w_s[16 * 576];
    __shared__ float in_s[16 * IN_CI_STRIDE];

    const int tid = threadIdx.x;
    const int co2 = tid & 31;
    const int h   = tid >> 5;
    const int x0 = blockIdx.x * 32, y0 = blockIdx.y * 2;
    const int b       = blockIdx.z >> 2;
    const int quarter = blockIdx.z & 3;

    {
        const float4* wsrc = (const float4*)(wt + quarter * 16 * 576);
        float4* wdst = (float4*)w_s;
#pragma unroll
        for (int i = 0; i < 9; i++)
            wdst[tid + i * 256] = wsrc[tid + i * 256];
    }
    if (SRC == 0) {
#pragma unroll
        for (int i = 0; i < 9; i++) {
            int e = i * 256 + tid;
            if (e < 2176) {
                int xx = e % 34;
                int t  = e / 34;
                int r  = t & 3;
                int ci = t >> 2;
                int y  = y0 - 1 + r;
                int xg = x0 - 1 + xx;
                float v = 0.f;
                if ((unsigned)y < 64u && (unsigned)xg < 64u)
                    v = in_x[((b * 64 + quarter * 16 + ci) * 64 + y) * 64 + xg];
                in_s[ci * IN_CI_STRIDE + r * 36 + xx] = v;
            }
        }
    } else {
        const int ci = tid & 15;
        const float bvin = in_bias[quarter * 16 + ci];
#pragma unroll
        for (int i = 0; i < 9; i++) {
            int e = i * 256 + tid;
            if (e < 2176) {
                int t  = e >> 4;
                int r  = t / 34;
                int xx = t - r * 34;
                int y  = y0 - 1 + r;
                int xg = x0 - 1 + xx;
                float v = 0.f;
                if ((unsigned)y < 64u && (unsigned)xg < 64u) {
                    int idx = ((b * 64 + y) * 64 + xg) * 64 + quarter * 16 + ci;
                    float s0 = g_p[idx]          + g_p[idx + PBUF];
                    float s1 = g_p[idx + 2*PBUF] + g_p[idx + 3*PBUF];
                    v = fmaxf(s0 + s1 + bvin, 0.f);
                }
                in_s[ci * IN_CI_STRIDE + r * 36 + xx] = v;
            }
        }
    }
    __syncthreads();

    ull accA[4] = {0,0,0,0};
    ull accB[4] = {0,0,0,0};

#pragma unroll 4
    for (int ci = 0; ci < 16; ci++) {
        const ull* wp = (const ull*)(w_s + ci * 576) + co2;
        ull w2[9];
#pragma unroll
        for (int k = 0; k < 9; k++) w2[k] = wp[k * 32];

        const float* ibase = in_s + ci * IN_CI_STRIDE + h * 4;
#pragma unroll
        for (int irow = 0; irow < 4; irow++) {
            float4 v0 = *(const float4*)(ibase + irow * 36);
            float2 v1 = *(const float2*)(ibase + irow * 36 + 4);
            ull d[6];
            d[0] = pack2(v0.x, v0.x); d[1] = pack2(v0.y, v0.y);
            d[2] = pack2(v0.z, v0.z); d[3] = pack2(v0.w, v0.w);
            d[4] = pack2(v1.x, v1.x); d[5] = pack2(v1.y, v1.y);
            if (irow < 3) {
#pragma unroll
                for (int p = 0; p < 4; p++) {
                    fma2(accA[p], w2[irow*3+0], d[p]);
                    fma2(accA[p], w2[irow*3+1], d[p+1]);
                    fma2(accA[p], w2[irow*3+2], d[p+2]);
                }
            }
            if (irow >= 1) {
#pragma unroll
                for (int p = 0; p < 4; p++) {
                    fma2(accB[p], w2[(irow-1)*3+0], d[p]);
                    fma2(accB[p], w2[(irow-1)*3+1], d[p+1]);
                    fma2(accB[p], w2[(irow-1)*3+2], d[p+2]);
                }
            }
        }
    }

    float* __restrict__ out = ((SRC == 0) ? g_p : g_q) + quarter * PBUF;
    int base = ((b * 64 + y0) * 64 + x0 + h * 4) * 64;
#pragma unroll
    for (int p = 0; p < 4; p++) {
        float a0, a1, b0v, b1v;
        unpack2(accA[p], a0, a1);
        unpack2(accB[p], b0v, b1v);
        out[base + p * 64 + co2]             = a0;
        out[base + p * 64 + co2 + 32]        = a1;
        out[base + 4096 + p * 64 + co2]      = b0v;
        out[base + 4096 + p * 64 + co2 + 32] = b1v;
    }
}

// ---------------- attention: 32 tokens/block, 512 threads, fused ----------------
// mapping (phases 1,2,3): tt = tid & 31 (token), cg = tid >> 5 (0..15), 4 ch/thread.
#define OFF_WQ 0
#define OFF_WK 4224
#define OFF_WV 8448
#define OFF_WO 12672
#define OFF_T  16896               // [32][65]
#define OFF_KV 18976               // float2 [32][65] (8B aligned: 18976*4 % 8 == 0)
#define OFF_O  23136               // [32][65]
#define OFF_SQ 25216               // [16][33]
#define OFF_SK 25744
#define SMEM_FLOATS 26272          // 105088 bytes

__global__ void __launch_bounds__(512) k_attn(
    const float* __restrict__ wq, const float* __restrict__ wk,
    const float* __restrict__ wv, const float* __restrict__ wo,
    const float* __restrict__ bo, const float* __restrict__ b2,
    float* __restrict__ out)
{
    extern __shared__ float sm[];
    float*  wq_s = sm + OFF_WQ;    // [l][c], stride 66
    float*  wk_s = sm + OFF_WK;
    float*  wv_s = sm + OFF_WV;
    float*  wo_s = sm + OFF_WO;
    float*  t_s  = sm + OFF_T;
    float2* kv_s = (float2*)(sm + OFF_KV);
    float*  o_s  = sm + OFF_O;
    float*  sq_s = sm + OFF_SQ;
    float*  sk_s = sm + OFF_SK;

    int tid = threadIdx.x;
    int n0  = blockIdx.x * 32;

    // stage weights transposed (coalesced reads, pad-66 conflict-free writes)
#pragma unroll
    for (int i = 0; i < 8; i++) {
        int gg = tid + i * 512;
        int c = gg >> 6, l = gg & 63;
        wq_s[l * 66 + c] = wq[gg];
        wk_s[l * 66 + c] = wk[gg];
        wv_s[l * 66 + c] = wv[gg];
        wo_s[l * 66 + c] = wo[gg];
    }
    // t = Σ4 conv2 partials + b2
#pragma unroll
    for (int i = 0; i < 4; i++) {
        int gg = tid + i * 512;
        int idx = n0 * 64 + gg;
        float s0 = g_q[idx]          + g_q[idx + PBUF];
        float s1 = g_q[idx + 2*PBUF] + g_q[idx + 3*PBUF];
        t_s[(gg >> 6) * 65 + (gg & 63)] = s0 + s1 + b2[gg & 63];
    }
    __syncthreads();

    const int tt = tid & 31;
    const int cg = tid >> 5;       // 0..15 (uniform per warp)
    const int c0 = cg * 4;

    // phase 1: q/k/v matvecs (4 channels each)
    ull q2[2] = {0,0}, k2[2] = {0,0}, v2[2] = {0,0};
    const float* trow = t_s + tt * 65;
#pragma unroll 4
    for (int l = 0; l < 64; l++) {
        float tl = trow[l];
        ull tl2 = pack2(tl, tl);
        const ull* wql = (const ull*)(wq_s + l * 66 + c0);
        const ull* wkl = (const ull*)(wk_s + l * 66 + c0);
        const ull* wvl = (const ull*)(wv_s + l * 66 + c0);
        fma2(q2[0], tl2, wql[0]); fma2(q2[1], tl2, wql[1]);
        fma2(k2[0], tl2, wkl[0]); fma2(k2[1], tl2, wkl[1]);
        fma2(v2[0], tl2, wvl[0]); fma2(v2[1], tl2, wvl[1]);
    }
    float q[4], kk[4], vv[4];
    unpack2(q2[0], q[0], q[1]);  unpack2(q2[1], q[2], q[3]);
    unpack2(k2[0], kk[0], kk[1]); unpack2(k2[1], kk[2], kk[3]);
    unpack2(v2[0], vv[0], vv[1]); unpack2(v2[1], vv[2], vv[3]);

    float sq = 0.f, sk = 0.f;
#pragma unroll
    for (int j = 0; j < 4; j++) { sq = fmaf(q[j], q[j], sq); sk = fmaf(kk[j], kk[j], sk); }
    sq_s[cg * 33 + tt] = sq;
    sk_s[cg * 33 + tt] = sk;
    __syncthreads();
    sq = 0.f; sk = 0.f;
#pragma unroll
    for (int m = 0; m < 16; m++) { sq += sq_s[m * 33 + tt]; sk += sk_s[m * 33 + tt]; }
    const float LOG2E = 1.4426950408889634f;
    float invq = LOG2E / fmaxf(sqrtf(sq), 1e-12f);
    float invk = 1.0f  / fmaxf(sqrtf(sk), 1e-12f);
#pragma unroll
    for (int j = 0; j < 4; j++) {
        q[j] *= invq;                                      // stays in regs
        kv_s[tt * 65 + c0 + j] = make_float2(kk[j] * invk, vv[j]);
    }
    __syncthreads();

    // phase 2: rank-1 softmax; packed num/den: fma2(nd, {e,e}, {v_d, 1})
    ull nd[4] = {0,0,0,0};
    const float2* kvrow = kv_s + tt * 65;
#pragma unroll 4
    for (int d = 0; d < 64; d++) {
        float2 kv = kvrow[d];
        ull vd2 = pack2(kv.y, 1.0f);
#pragma unroll
        for (int j = 0; j < 4; j++) {
            float e = ex2f(q[j] * kv.x);
            fma2(nd[j], pack2(e, e), vd2);
        }
    }
#pragma unroll
    for (int j = 0; j < 4; j++) {
        float num, den;
        unpack2(nd[j], num, den);
        o_s[tt * 65 + c0 + j] = __fdividef(num, den);
    }
    __syncthreads();

    // phase 3: Wo projection + bias + residual; coalesced NCHW stores
    ull fin2[2] = {0,0};
    const float* orow = o_s + tt * 65;
#pragma unroll 4
    for (int c = 0; c < 64; c++) {
        float oc = orow[c];
        ull oc2 = pack2(oc, oc);
        const ull* wol = (const ull*)(wo_s + c * 66 + c0);
        fma2(fin2[0], oc2, wol[0]);
        fma2(fin2[1], oc2, wol[1]);
    }
    int b = n0 >> 12;
    int s = (n0 & 4095) + tt;
#pragma unroll
    for (int j = 0; j < 2; j++) {
        float f0, f1;
        unpack2(fin2[j], f0, f1);
        int ch = c0 + 2 * j;
        f0 += bo[ch]     + t_s[tt * 65 + ch];
        f1 += bo[ch + 1] + t_s[tt * 65 + ch + 1];
        out[(b * 64 + ch    ) * 4096 + s] = f0;
        out[(b * 64 + ch + 1) * 4096 + s] = f1;
    }
}

// ---------------- launch ----------------
extern "C" void kernel_launch(void* const* d_in, const int* in_sizes, int n_in,
                              void* d_out, int out_size) {
    const float* x  = (const float*)d_in[0];
    const float* w1 = (const float*)d_in[1];
    const float* b1 = (const float*)d_in[2];
    const float* w2 = (const float*)d_in[3];
    const float* b2 = (const float*)d_in[4];
    const float* wq = (const float*)d_in[5];
    const float* wk = (const float*)d_in[6];
    const float* wv = (const float*)d_in[7];
    const float* wo = (const float*)d_in[8];
    const float* bo = (const float*)d_in[9];
    float* out = (float*)d_out;

    cudaFuncSetAttribute(k_attn, cudaFuncAttributeMaxDynamicSharedMemorySize,
                         SMEM_FLOATS * (int)sizeof(float));

    k_transpose_w<<<(2 * 36864 + 255) / 256, 256>>>(w1, w2);
    k_conv<0><<<dim3(2, 32, 8), dim3(256)>>>(x, b1);
    k_conv<1><<<dim3(2, 32, 8), dim3(256)>>>(x, b1);
    k_attn<<<256, 512, SMEM_FLOATS * (int)sizeof(float)>>>(wq, wk, wv, wo, bo, b2, out);
}